// round 11
// baseline (speedup 1.0000x reference)
#include <cuda_runtime.h>

// Problem constants (fixed by the reference)
#define BB 16
#define SS 2048
#define HH 1024

#define NPROD 256          // producer blocks for u2 (must be < wave-1 capacity)

// Folded projection vector u2[j] = sum_h v[h] * attn_w[h, H+j].
// Invariant: g_u2 == 0 and g_done == 0 at entry of every kernel_launch call.
// Zero at module load; softmax_kernel restores both at the end of each call.
__device__ float g_u2[HH];
__device__ int   g_done;

// ---------------------------------------------------------------------------
// Fused kernel: blocks 0..NPROD-1 first accumulate u2 (4 MB coalesced read of
// attn_w's second half, REDG atomics into g_u2), then signal a counter.
// ALL blocks spin on the counter (thread-0 volatile poll), fence, stage u2
// into smem (L2-coherent __ldcg), and compute 16 score rows each.
// ---------------------------------------------------------------------------
__global__ __launch_bounds__(512) void fused_kernel(
    const float* __restrict__ attn_w,  // [H, 2H] row-major
    const float* __restrict__ v,       // [1, H]
    const float* __restrict__ enc,     // [B, S, H]
    float* __restrict__ out)           // [B*S] scores (in d_out)
{
    const int tid  = threadIdx.x;
    const int warp = tid >> 5;          // 0..15
    const int lane = tid & 31;
    const int bid  = blockIdx.x;

    __shared__ float4 su2[HH / 4];      // 4 KB, reused for both phases

    // ---- Phase 1: u2 producers ----
    if (bid < NPROD) {
        const int j0 = (bid & 7) * 128;       // 128-column tile (32 x float4)
        const int h0 = (bid >> 3) * 32;       // 32-row h-chunk

        const float4* base = reinterpret_cast<const float4*>(attn_w + HH + j0) + lane;
        const size_t rstride = (2 * HH) / 4;

        // warp w covers rows h0+w and h0+w+16 (2 independent loads/thread)
        float4 acc;
        {
            const int h1 = h0 + warp, h2 = h0 + warp + 16;
            const float v1 = __ldg(v + h1), v2 = __ldg(v + h2);
            const float4 w1 = __ldg(base + (size_t)h1 * rstride);
            const float4 w2 = __ldg(base + (size_t)h2 * rstride);
            acc.x = v1 * w1.x + v2 * w2.x;
            acc.y = v1 * w1.y + v2 * w2.y;
            acc.z = v1 * w1.z + v2 * w2.z;
            acc.w = v1 * w1.w + v2 * w2.w;
        }
        __shared__ float4 part[16][32];
        part[warp][lane] = acc;
        __syncthreads();

        if (warp == 0) {
            float4 s = part[0][lane];
#pragma unroll
            for (int w = 1; w < 16; ++w) {
                const float4 p = part[w][lane];
                s.x += p.x; s.y += p.y; s.z += p.z; s.w += p.w;
            }
            float* dst = g_u2 + j0 + lane * 4;
            atomicAdd(dst + 0, s.x);
            atomicAdd(dst + 1, s.y);
            atomicAdd(dst + 2, s.z);
            atomicAdd(dst + 3, s.w);
        }
        __syncthreads();
        // Publish: all g_u2 atomics from this block are done.
        if (tid == 0) {
            __threadfence();
            atomicAdd(&g_done, 1);
        }
    }

    // ---- Barrier: wait until all NPROD producer blocks have published ----
    if (tid == 0) {
        while (*((volatile int*)&g_done) != NPROD)
            __nanosleep(64);
    }
    __syncthreads();
    __threadfence();   // acquire: order g_u2 reads after the flag observation

    // ---- Phase 2: stage u2 (L2-coherent loads), compute 16 score rows ----
    if (tid < HH / 4)
        su2[tid] = __ldcg(reinterpret_cast<const float4*>(g_u2) + tid);
    __syncthreads();

    const int row = bid * 16 + warp;    // 0 .. B*S-1
    const float4* e = reinterpret_cast<const float4*>(enc) + (size_t)row * (HH / 4);

    float acc = 0.f;
#pragma unroll
    for (int it = 0; it < 8; ++it) {
        const float4 ev = __ldcs(e + it * 32 + lane);   // streaming: no reuse
        const float4 uv = su2[it * 32 + lane];
        acc += ev.x * uv.x + ev.y * uv.y + ev.z * uv.z + ev.w * uv.w;
    }
#pragma unroll
    for (int m = 16; m; m >>= 1)
        acc += __shfl_xor_sync(0xffffffffu, acc, m);
    if (lane == 0) out[row] = acc;
}

// ---------------------------------------------------------------------------
// Kernel 2: in-place row softmax over S=2048, one block per batch row.
// Also restores the g_u2 == 0 / g_done == 0 invariant for the next replay.
// ---------------------------------------------------------------------------
__global__ __launch_bounds__(256) void softmax_kernel(float* __restrict__ out)
{
    __shared__ float red[8];
    float* row = out + (size_t)blockIdx.x * SS;
    const int tid  = threadIdx.x;
    const int warp = tid >> 5;
    const int lane = tid & 31;

    // Reset globals for the next call (runs after fused_kernel completed).
    if (blockIdx.x == 0) {
        reinterpret_cast<float4*>(g_u2)[tid] = make_float4(0.f, 0.f, 0.f, 0.f);
        if (tid == 0) g_done = 0;
    }

    float x[8];
    float mx = -1e30f;
#pragma unroll
    for (int i = 0; i < 8; ++i) {
        x[i] = row[tid + i * 256];
        mx = fmaxf(mx, x[i]);
    }
#pragma unroll
    for (int m = 16; m; m >>= 1)
        mx = fmaxf(mx, __shfl_xor_sync(0xffffffffu, mx, m));
    if (lane == 0) red[warp] = mx;
    __syncthreads();
    float bmax = red[0];
#pragma unroll
    for (int i = 1; i < 8; ++i) bmax = fmaxf(bmax, red[i]);
    __syncthreads();

    float s = 0.f;
#pragma unroll
    for (int i = 0; i < 8; ++i) {
        x[i] = __expf(x[i] - bmax);
        s += x[i];
    }
#pragma unroll
    for (int m = 16; m; m >>= 1)
        s += __shfl_xor_sync(0xffffffffu, s, m);
    if (lane == 0) red[warp] = s;
    __syncthreads();
    float tot = 0.f;
#pragma unroll
    for (int i = 0; i < 8; ++i) tot += red[i];
    const float inv = 1.0f / tot;

#pragma unroll
    for (int i = 0; i < 8; ++i)
        row[tid + i * 256] = x[i] * inv;
}

// ---------------------------------------------------------------------------
// Inputs (metadata order): hidden [B,1,H], encoder_outputs [B,S,H],
//                          attn_w [H,2H], attn_b [H], v [1,H]
// hidden and attn_b are provably unused (softmax shift invariance folds them
// into a per-row constant).
// Output: [B,1,S] float32.
// ---------------------------------------------------------------------------
extern "C" void kernel_launch(void* const* d_in, const int* in_sizes, int n_in,
                              void* d_out, int out_size)
{
    const float* enc    = (const float*)d_in[1];
    const float* attn_w = (const float*)d_in[2];
    const float* v      = (const float*)d_in[4];
    float* out = (float*)d_out;

    fused_kernel<<<(BB * SS) / 16, 512>>>(attn_w, v, enc, out);
    softmax_kernel<<<BB, 256>>>(out);
}